// round 16
// baseline (speedup 1.0000x reference)
#include <cuda_runtime.h>
#include <cuda_fp16.h>
#include <math.h>
#include <stdint.h>

#define BBATCH 8
#define SQLEN  256
#define SKVLEN 1024
#define DMODEL 1024
#define NHEADS 16
#define DHEAD  64
#define DFFN   4096
#define QROWS  (BBATCH*SQLEN)
#define KVROWS (BBATCH*SKVLEN)
#define OUT_ELEMS  ((size_t)QROWS*DMODEL)
#define ATTN_ELEMS ((size_t)BBATCH*NHEADS*SQLEN*SKVLEN)

// ----------------------------- scratch -----------------------------------
__device__ __half g_qln_h [QROWS*DMODEL];
__device__ __half g_kvln_h[KVROWS*DMODEL];
__device__ __half g_Qh [QROWS*DMODEL];
__device__ __half g_Kh [KVROWS*DMODEL];
__device__ __half g_Vt [KVROWS*DMODEL];
__device__ __half g_attn_h[BBATCH*NHEADS*SQLEN*SKVLEN];
__device__ __half g_ctx_h[QROWS*DMODEL];
__device__ __half g_y_h [QROWS*DMODEL];
__device__ __half g_hh  [QROWS*DFFN];
__device__ __half g_Wqt[DMODEL*DMODEL];
__device__ __half g_Wkt[DMODEL*DMODEL];
__device__ __half g_Wvt[DMODEL*DMODEL];
__device__ __half g_Wot[DMODEL*DMODEL];
__device__ __half g_W1t[DFFN*DMODEL];
__device__ __half g_W2t[DMODEL*DFFN];
__device__ float  g_x [QROWS*DMODEL];
__device__ float  g_attn_fb[BBATCH*NHEADS*SQLEN*SKVLEN];

// ------------------ weight transposes (splittable by id) ------------------
__global__ void __launch_bounds__(256) transpose_part_kernel(
    const float* __restrict__ Wq, const float* __restrict__ Wk,
    const float* __restrict__ Wv, const float* __restrict__ Wo,
    const float* __restrict__ W1, const float* __restrict__ W2,
    __half* __restrict__ Wqt, __half* __restrict__ Wkt,
    __half* __restrict__ Wvt, __half* __restrict__ Wot,
    __half* __restrict__ W1t, __half* __restrict__ W2t, int id_base)
{
    __shared__ float t[32][33];
    const int id = blockIdx.x + id_base;
    const float* W; __half* Wt; int K, N, local, tilesX;
    if (id < 4096) {
        K = DMODEL; N = DMODEL; tilesX = 32; local = id & 1023;
        const int w = id >> 10;
        W  = (w == 0) ? Wq  : (w == 1) ? Wk  : (w == 2) ? Wv  : Wo;
        Wt = (w == 0) ? Wqt : (w == 1) ? Wkt : (w == 2) ? Wvt : Wot;
    } else if (id < 8192) {
        K = DMODEL; N = DFFN; tilesX = 128; local = id - 4096; W = W1; Wt = W1t;
    } else {
        K = DFFN; N = DMODEL; tilesX = 32; local = id - 8192; W = W2; Wt = W2t;
    }
    const int n0 = (local % tilesX) * 32, k0 = (local / tilesX) * 32;
    const int x = threadIdx.x & 31, y = threadIdx.x >> 5;
    #pragma unroll
    for (int i = 0; i < 32; i += 8)
        t[y + i][x] = W[(size_t)(k0 + y + i) * N + n0 + x];
    __syncthreads();
    #pragma unroll
    for (int i = 0; i < 32; i += 8)
        Wt[(size_t)(n0 + y + i) * K + k0 + x] = __float2half_rn(t[x][y + i]);
}

// -------------- LayerNorm, warp-per-row (8 rows / 256-thr CTA) -----------
__global__ void __launch_bounds__(256) ln_w_kernel(const float* __restrict__ x,
                                                   const float* __restrict__ g,
                                                   const float* __restrict__ b,
                                                   __half* __restrict__ y) {
    const int warp = threadIdx.x >> 5, lane = threadIdx.x & 31;
    const int row = blockIdx.x * 8 + warp;
    const float4* px = (const float4*)(x + (size_t)row * DMODEL);
    float4 v[8];
    float s = 0.f, q2 = 0.f;
    #pragma unroll
    for (int i = 0; i < 8; ++i) {
        v[i] = px[i * 32 + lane];
        s  += v[i].x + v[i].y + v[i].z + v[i].w;
        q2 += v[i].x*v[i].x + v[i].y*v[i].y + v[i].z*v[i].z + v[i].w*v[i].w;
    }
    #pragma unroll
    for (int o = 16; o > 0; o >>= 1) {
        s  += __shfl_xor_sync(0xffffffffu, s,  o);
        q2 += __shfl_xor_sync(0xffffffffu, q2, o);
    }
    const float mu  = s * (1.0f / DMODEL);
    const float inv = rsqrtf(q2 * (1.0f / DMODEL) - mu * mu + 1e-5f);
    uint2* py = (uint2*)(y + (size_t)row * DMODEL);
    #pragma unroll
    for (int i = 0; i < 8; ++i) {
        const float4 gv = ((const float4*)g)[i * 32 + lane];
        const float4 bv = ((const float4*)b)[i * 32 + lane];
        __half2 h0 = __floats2half2_rn((v[i].x - mu)*inv*gv.x + bv.x,
                                       (v[i].y - mu)*inv*gv.y + bv.y);
        __half2 h1 = __floats2half2_rn((v[i].z - mu)*inv*gv.z + bv.z,
                                       (v[i].w - mu)*inv*gv.w + bv.w);
        uint2 o2;
        o2.x = *reinterpret_cast<uint32_t*>(&h0);
        o2.y = *reinterpret_cast<uint32_t*>(&h1);
        py[i * 32 + lane] = o2;
    }
}

// -------- softmax, warp-per-row: fp32 in place + fused fp16 copy ---------
__global__ void __launch_bounds__(256) softmax_w_kernel(float* __restrict__ attn,
                                                        __half* __restrict__ attn_h) {
    const int warp = threadIdx.x >> 5, lane = threadIdx.x & 31;
    const size_t row = (size_t)blockIdx.x * 8 + warp;
    float4* p = (float4*)(attn + row * SKVLEN);
    float4 v[8];
    float m = -1e30f;
    #pragma unroll
    for (int i = 0; i < 8; ++i) {
        v[i] = p[i * 32 + lane];
        m = fmaxf(m, fmaxf(fmaxf(v[i].x, v[i].y), fmaxf(v[i].z, v[i].w)));
    }
    #pragma unroll
    for (int o = 16; o > 0; o >>= 1)
        m = fmaxf(m, __shfl_xor_sync(0xffffffffu, m, o));
    float s = 0.f;
    #pragma unroll
    for (int i = 0; i < 8; ++i) {
        v[i].x = __expf(v[i].x - m); v[i].y = __expf(v[i].y - m);
        v[i].z = __expf(v[i].z - m); v[i].w = __expf(v[i].w - m);
        s += v[i].x + v[i].y + v[i].z + v[i].w;
    }
    #pragma unroll
    for (int o = 16; o > 0; o >>= 1)
        s += __shfl_xor_sync(0xffffffffu, s, o);
    const float inv = 1.0f / s;
    uint2* ph = (uint2*)(attn_h + row * SKVLEN);
    #pragma unroll
    for (int i = 0; i < 8; ++i) {
        v[i].x *= inv; v[i].y *= inv; v[i].z *= inv; v[i].w *= inv;
        p[i * 32 + lane] = v[i];
        __half2 h0 = __floats2half2_rn(v[i].x, v[i].y);
        __half2 h1 = __floats2half2_rn(v[i].z, v[i].w);
        uint2 o2;
        o2.x = *reinterpret_cast<uint32_t*>(&h0);
        o2.y = *reinterpret_cast<uint32_t*>(&h1);
        ph[i * 32 + lane] = o2;
    }
}

// ----------------------------- fp16 MMA helpers --------------------------
__device__ __forceinline__ void ldsm4(uint32_t (&d)[4], uint32_t addr) {
    asm volatile("ldmatrix.sync.aligned.m8n8.x4.shared.b16 {%0,%1,%2,%3}, [%4];"
        : "=r"(d[0]), "=r"(d[1]), "=r"(d[2]), "=r"(d[3]) : "r"(addr));
}
__device__ __forceinline__ void mma_f16(float (&c)[4], const uint32_t (&a)[4],
                                        const uint32_t (&b)[2]) {
    asm volatile("mma.sync.aligned.m16n8k16.row.col.f32.f16.f16.f32 "
        "{%0,%1,%2,%3},{%4,%5,%6,%7},{%8,%9},{%0,%1,%2,%3};"
        : "+f"(c[0]), "+f"(c[1]), "+f"(c[2]), "+f"(c[3])
        : "r"(a[0]), "r"(a[1]), "r"(a[2]), "r"(a[3]), "r"(b[0]), "r"(b[1]));
}

// Epilogue modes
template<int MODE>
__device__ __forceinline__ void store_elem(void* __restrict__ Cv,
                                           const float* __restrict__ bias,
                                           const float* __restrict__ res,
                                           int N, int bz, int row, int col, float v) {
    if (MODE == 0) {
        ((float*)Cv)[(size_t)row*N + col] = v + bias[col];
    } else if (MODE == 1) {
        float x = v + bias[col];
        ((__half*)Cv)[(size_t)row*N + col] =
            __float2half_rn(0.5f*x*(1.0f + erff(x*0.70710678118654752f)));
    } else if (MODE == 2) {
        ((float*)Cv)[(size_t)row*N + col] = v + bias[col] + res[(size_t)row*N + col];
    } else if (MODE == 3) {
        ((__half*)Cv)[(size_t)(row>>8)*(NHEADS*SQLEN*DHEAD) + (size_t)(col>>6)*(SQLEN*DHEAD)
          + (size_t)(row&255)*DHEAD + (col&63)] = __float2half_rn(v + bias[col]);
    } else if (MODE == 4) {
        ((__half*)Cv)[(size_t)(row>>10)*(NHEADS*SKVLEN*DHEAD) + (size_t)(col>>6)*(SKVLEN*DHEAD)
          + (size_t)(row&1023)*DHEAD + (col&63)] = __float2half_rn(v + bias[col]);
    } else if (MODE == 5) {
        ((__half*)Cv)[(size_t)(row>>10)*(NHEADS*DHEAD*SKVLEN) + (size_t)(col>>6)*(DHEAD*SKVLEN)
          + (size_t)(col&63)*SKVLEN + (row&1023)] = __float2half_rn(v + bias[col]);
    } else if (MODE == 6) {
        ((float*)Cv)[(size_t)bz*(SQLEN*SKVLEN) + (size_t)row*SKVLEN + col] = v * 0.125f;
    } else if (MODE == 7) {
        ((__half*)Cv)[((size_t)(bz>>4)*SQLEN + row)*DMODEL + (size_t)(bz&15)*DHEAD + col] =
            __float2half_rn(v);
    }
}

// ---- fp16 NT GEMM: BK=32, STAGES-unrolled mainloop (static smem slots) ---
// requires (K/32) % STAGES == 0
template<int BM, int BN, int WM, int WN, int STAGES, int MODE>
__global__ void __launch_bounds__(WM*WN*32, 3) hgemm_nt(
    const __half* __restrict__ Ag, const __half* __restrict__ Bg,
    const float* __restrict__ bias, const float* __restrict__ res,
    void* __restrict__ Cg, int N, int K, long sA, long sB)
{
    constexpr int NTH  = WM*WN*32;
    constexpr int ROWB = 80;
    constexpr int STGB = (BM + BN) * ROWB;
    constexpr int MT = BM / (WM * 16);
    constexpr int NT = BN / (WN * 8);
    extern __shared__ __align__(16) __half dynsm[];
    const uint32_t sm0 = (uint32_t)__cvta_generic_to_shared(dynsm);

    const int tid  = threadIdx.x;
    const int warp = tid >> 5, lane = tid & 31;
    const int wm0 = (warp % WM) * (BM / WM);
    const int wn0 = (warp / WM) * (BN / WN);
    const int bm0 = blockIdx.y * BM;
    const int bn0 = blockIdx.x * BN;
    const int bz  = blockIdx.z;
    const __half* A = Ag + (size_t)bz * sA + (size_t)bm0 * K;
    const __half* B = Bg + (size_t)bz * sB + (size_t)bn0 * K;

    float acc[MT][NT][4];
    #pragma unroll
    for (int i = 0; i < MT; ++i)
        #pragma unroll
        for (int j = 0; j < NT; ++j)
            { acc[i][j][0]=0.f; acc[i][j][1]=0.f; acc[i][j][2]=0.f; acc[i][j][3]=0.f; }

    const int KT = K >> 5;

    // prefetch k-tile `it` into smem slot at byte base `sb` (compile-time)
    auto prefetch = [&](int it, uint32_t sb) {
        if (it < KT) {
            const __half* Ak = A + it * 32;
            const __half* Bk = B + it * 32;
            #pragma unroll
            for (int i = tid; i < (BM + BN) * 4; i += NTH) {
                const int r = i >> 2, c = i & 3;
                uint32_t dst; const __half* src;
                if (r < BM) { dst = sb + (uint32_t)(r*ROWB + c*16); src = Ak + (size_t)r*K + c*8; }
                else { dst = sb + (uint32_t)(BM*ROWB + (r-BM)*ROWB + c*16);
                       src = Bk + (size_t)(r-BM)*K + c*8; }
                asm volatile("cp.async.cg.shared.global [%0], [%1], 16;" :: "r"(dst), "l"(src));
            }
        }
        asm volatile("cp.async.commit_group;" ::: "memory");
    };

    uint32_t afA[MT][4], bfA[NT][2], afB[MT][4], bfB[NT][2];
    const int lr = lane & 15;

    auto ldfrag = [&](uint32_t sb, int ks,
                      uint32_t (&af)[MT][4], uint32_t (&bf)[NT][2]) {
        const uint32_t sbB = sb + BM*ROWB;
        const int lcb = ((lane >> 4) * 8 + ks * 16) * 2;
        #pragma unroll
        for (int mt = 0; mt < MT; ++mt)
            ldsm4(af[mt], sb + (uint32_t)((wm0 + mt*16 + lr)*ROWB + lcb));
        #pragma unroll
        for (int nt2 = 0; nt2 < NT/2; ++nt2) {
            uint32_t d[4];
            ldsm4(d, sbB + (uint32_t)((wn0 + nt2*16 + lr)*ROWB + lcb));
            bf[nt2*2  ][0] = d[0]; bf[nt2*2  ][1] = d[2];
            bf[nt2*2+1][0] = d[1]; bf[nt2*2+1][1] = d[3];
        }
    };
    auto mma_all = [&](const uint32_t (&af)[MT][4], const uint32_t (&bf)[NT][2]) {
        #pragma unroll
        for (int mt = 0; mt < MT; ++mt)
            #pragma unroll
            for (int nt = 0; nt < NT; ++nt)
                mma_f16(acc[mt][nt], af[mt], bf[nt]);
    };

    #pragma unroll
    for (int p = 0; p < STAGES - 1; ++p) prefetch(p, sm0 + (uint32_t)(p * STGB));
    asm volatile("cp.async.wait_group %0;" :: "n"(STAGES - 2) : "memory");
    __syncthreads();
    ldfrag(sm0, 0, afA, bfA);

    // mainloop unrolled by STAGES: slot indices are compile-time constants
    for (int kt = 0; kt < KT; kt += STAGES) {
        #pragma unroll
        for (int j = 0; j < STAGES; ++j) {
            const uint32_t sb = sm0 + (uint32_t)(j * STGB);
            ldfrag(sb, 1, afB, bfB);
            mma_all(afA, bfA);
            prefetch(kt + j + STAGES - 1,
                     sm0 + (uint32_t)(((j + STAGES - 1) % STAGES) * STGB));
            if (kt + j + 1 < KT) {
                asm volatile("cp.async.wait_group %0;" :: "n"(STAGES - 2) : "memory");
                __syncthreads();
                ldfrag(sm0 + (uint32_t)(((j + 1) % STAGES) * STGB), 0, afA, bfA);
            }
            mma_all(afB, bfB);
        }
    }

    const int g = lane >> 2, t = lane & 3;
    #pragma unroll
    for (int mt = 0; mt < MT; ++mt) {
        #pragma unroll
        for (int nt = 0; nt < NT; ++nt) {
            const int r0 = bm0 + wm0 + mt*16 + g;
            const int c0 = bn0 + wn0 + nt*8 + t*2;
            store_elem<MODE>(Cg, bias, res, N, bz, r0,     c0,     acc[mt][nt][0]);
            store_elem<MODE>(Cg, bias, res, N, bz, r0,     c0 + 1, acc[mt][nt][1]);
            store_elem<MODE>(Cg, bias, res, N, bz, r0 + 8, c0,     acc[mt][nt][2]);
            store_elem<MODE>(Cg, bias, res, N, bz, r0 + 8, c0 + 1, acc[mt][nt][3]);
        }
    }
}

// ----------------------------- launch ------------------------------------
#define SMEMB(BM, BN, S) ((S) * ((BM) + (BN)) * 80)

extern "C" void kernel_launch(void* const* d_in, const int* in_sizes, int n_in,
                              void* d_out, int out_size) {
    const float* memory = (const float*)d_in[0];
    const float* q      = (const float*)d_in[1];
    const float* Wq = (const float*)d_in[2];  const float* bq = (const float*)d_in[3];
    const float* Wk = (const float*)d_in[4];  const float* bk = (const float*)d_in[5];
    const float* Wv = (const float*)d_in[6];  const float* bv = (const float*)d_in[7];
    const float* Wo = (const float*)d_in[8];  const float* bo = (const float*)d_in[9];
    const float* g_kv = (const float*)d_in[10]; const float* b_kv = (const float*)d_in[11];
    const float* g_q  = (const float*)d_in[12]; const float* b_q  = (const float*)d_in[13];
    const float* g_ff = (const float*)d_in[14]; const float* b_ff = (const float*)d_in[15];
    const float* W1 = (const float*)d_in[16]; const float* b1 = (const float*)d_in[17];
    const float* W2 = (const float*)d_in[18]; const float* b2 = (const float*)d_in[19];

    __half *p_qln, *p_kvln, *p_Qh, *p_Kh, *p_Vt, *p_attn_h, *p_ctx, *p_y, *p_h;
    __half *p_Wqt, *p_Wkt, *p_Wvt, *p_Wot, *p_W1t, *p_W2t;
    float *p_x, *p_fb;
    cudaGetSymbolAddress((void**)&p_qln,  g_qln_h);
    cudaGetSymbolAddress((void**)&p_kvln, g_kvln_h);
    cudaGetSymbolAddress((void**)&p_Qh,   g_Qh);
    cudaGetSymbolAddress((void**)&p_Kh,   g_Kh);
    cudaGetSymbolAddress((void**)&p_Vt,   g_Vt);
    cudaGetSymbolAddress((void**)&p_attn_h, g_attn_h);
    cudaGetSymbolAddress((void**)&p_ctx,  g_ctx_h);
    cudaGetSymbolAddress((void**)&p_y,    g_y_h);
    cudaGetSymbolAddress((void**)&p_h,    g_hh);
    cudaGetSymbolAddress((void**)&p_Wqt,  g_Wqt);
    cudaGetSymbolAddress((void**)&p_Wkt,  g_Wkt);
    cudaGetSymbolAddress((void**)&p_Wvt,  g_Wvt);
    cudaGetSymbolAddress((void**)&p_Wot,  g_Wot);
    cudaGetSymbolAddress((void**)&p_W1t,  g_W1t);
    cudaGetSymbolAddress((void**)&p_W2t,  g_W2t);
    cudaGetSymbolAddress((void**)&p_x,    g_x);
    cudaGetSymbolAddress((void**)&p_fb,   g_attn_fb);

    float* out = (float*)d_out;
    float* attn = ((size_t)out_size >= OUT_ELEMS + ATTN_ELEMS) ? (out + OUT_ELEMS) : p_fb;

    cudaFuncSetAttribute(hgemm_nt<64,128,2,2,4,3>, cudaFuncAttributeMaxDynamicSharedMemorySize, SMEMB(64,128,4));
    cudaFuncSetAttribute(hgemm_nt<64,128,2,2,4,4>, cudaFuncAttributeMaxDynamicSharedMemorySize, SMEMB(64,128,4));
    cudaFuncSetAttribute(hgemm_nt<64,128,2,2,4,5>, cudaFuncAttributeMaxDynamicSharedMemorySize, SMEMB(64,128,4));
    cudaFuncSetAttribute(hgemm_nt<64,128,2,2,2,6>, cudaFuncAttributeMaxDynamicSharedMemorySize, SMEMB(64,128,2));
    cudaFuncSetAttribute(hgemm_nt<64,64,2,2,4,7>,  cudaFuncAttributeMaxDynamicSharedMemorySize, SMEMB(64,64,4));
    cudaFuncSetAttribute(hgemm_nt<64,128,2,2,4,0>, cudaFuncAttributeMaxDynamicSharedMemorySize, SMEMB(64,128,4));
    cudaFuncSetAttribute(hgemm_nt<64,128,2,2,4,1>, cudaFuncAttributeMaxDynamicSharedMemorySize, SMEMB(64,128,4));
    cudaFuncSetAttribute(hgemm_nt<64,128,2,2,4,2>, cudaFuncAttributeMaxDynamicSharedMemorySize, SMEMB(64,128,4));

    static cudaStream_t sB = nullptr, sC = nullptr;
    static cudaEvent_t ev0 = nullptr, evT = nullptr, evKV = nullptr,
                       evQ = nullptr, evV = nullptr, evFT = nullptr;
    if (sB == nullptr) {
        cudaStreamCreateWithFlags(&sB, cudaStreamNonBlocking);
        cudaStreamCreateWithFlags(&sC, cudaStreamNonBlocking);
        cudaEventCreateWithFlags(&ev0,  cudaEventDisableTiming);
        cudaEventCreateWithFlags(&evT,  cudaEventDisableTiming);
        cudaEventCreateWithFlags(&evKV, cudaEventDisableTiming);
        cudaEventCreateWithFlags(&evQ,  cudaEventDisableTiming);
        cudaEventCreateWithFlags(&evV,  cudaEventDisableTiming);
        cudaEventCreateWithFlags(&evFT, cudaEventDisableTiming);
    }
    cudaStream_t s0 = 0;

    cudaEventRecord(ev0, s0);
    cudaStreamWaitEvent(sB, ev0, 0);
    cudaStreamWaitEvent(sC, ev0, 0);

    // stream C: FFN weight transposes (off critical path)
    transpose_part_kernel<<<8192, 256, 0, sC>>>(Wq, Wk, Wv, Wo, W1, W2,
        p_Wqt, p_Wkt, p_Wvt, p_Wot, p_W1t, p_W2t, 4096);
    cudaEventRecord(evFT, sC);

    // main: QKVO transposes -> LN_kv (warp-per-row)
    transpose_part_kernel<<<4096, 256, 0, s0>>>(Wq, Wk, Wv, Wo, W1, W2,
        p_Wqt, p_Wkt, p_Wvt, p_Wot, p_W1t, p_W2t, 0);
    cudaEventRecord(evT, s0);
    ln_w_kernel<<<KVROWS/8, 256, 0, s0>>>(memory, g_kv, b_kv, p_kvln);
    cudaEventRecord(evKV, s0);

    // stream B: LN_q -> Q projection
    ln_w_kernel<<<QROWS/8, 256, 0, sB>>>(q, g_q, b_q, p_qln);
    cudaStreamWaitEvent(sB, evT, 0);
    hgemm_nt<64,128,2,2,4,3><<<dim3(8, 32), 128, SMEMB(64,128,4), sB>>>(
        p_qln, p_Wqt, bq, nullptr, p_Qh, DMODEL, DMODEL, 0, 0);
    cudaEventRecord(evQ, sB);

    // stream C: V projection
    cudaStreamWaitEvent(sC, evKV, 0);
    hgemm_nt<64,128,2,2,4,5><<<dim3(8, 128), 128, SMEMB(64,128,4), sC>>>(
        p_kvln, p_Wvt, bv, nullptr, p_Vt, DMODEL, DMODEL, 0, 0);
    cudaEventRecord(evV, sC);

    // main: K projection
    hgemm_nt<64,128,2,2,4,4><<<dim3(8, 128), 128, SMEMB(64,128,4), s0>>>(
        p_kvln, p_Wkt, bk, nullptr, p_Kh, DMODEL, DMODEL, 0, 0);

    // join Q, scores (KT=2, STAGES=2)
    cudaStreamWaitEvent(s0, evQ, 0);
    hgemm_nt<64,128,2,2,2,6><<<dim3(8, 4, BBATCH*NHEADS), 128, SMEMB(64,128,2), s0>>>(
        p_Qh, p_Kh, nullptr, nullptr, attn, SKVLEN, DHEAD,
        (long)SQLEN*DHEAD, (long)SKVLEN*DHEAD);

    // softmax (warp-per-row) + fp16 copy
    softmax_w_kernel<<<(BBATCH*NHEADS*SQLEN)/8, 256, 0, s0>>>(attn, p_attn_h);

    // join V, ctx
    cudaStreamWaitEvent(s0, evV, 0);
    hgemm_nt<64,64,2,2,4,7><<<dim3(1, 4, BBATCH*NHEADS), 128, SMEMB(64,64,4), s0>>>(
        p_attn_h, p_Vt, nullptr, nullptr, p_ctx, DHEAD, SKVLEN,
        (long)SQLEN*SKVLEN, (long)DHEAD*SKVLEN);

    // O projection
    hgemm_nt<64,128,2,2,4,0><<<dim3(8, 32), 128, SMEMB(64,128,4), s0>>>(
        p_ctx, p_Wot, bo, nullptr, p_x, DMODEL, DMODEL, 0, 0);

    // FFN
    ln_w_kernel<<<QROWS/8, 256, 0, s0>>>(p_x, g_ff, b_ff, p_y);
    cudaStreamWaitEvent(s0, evFT, 0);
    hgemm_nt<64,128,2,2,4,1><<<dim3(32, 32), 128, SMEMB(64,128,4), s0>>>(
        p_y, p_W1t, b1, nullptr, p_h, DFFN, DMODEL, 0, 0);
    hgemm_nt<64,128,2,2,4,2><<<dim3(8, 32), 128, SMEMB(64,128,4), s0>>>(
        p_h, p_W2t, b2, p_x, out, DMODEL, DFFN, 0, 0);
}

// round 17
// speedup vs baseline: 1.0301x; 1.0301x over previous
#include <cuda_runtime.h>
#include <cuda_fp16.h>
#include <math.h>
#include <stdint.h>

#define BBATCH 8
#define SQLEN  256
#define SKVLEN 1024
#define DMODEL 1024
#define NHEADS 16
#define DHEAD  64
#define DFFN   4096
#define QROWS  (BBATCH*SQLEN)
#define KVROWS (BBATCH*SKVLEN)
#define OUT_ELEMS  ((size_t)QROWS*DMODEL)
#define ATTN_ELEMS ((size_t)BBATCH*NHEADS*SQLEN*SKVLEN)

// ----------------------------- scratch -----------------------------------
__device__ __half g_qln_h [QROWS*DMODEL];
__device__ __half g_kvln_h[KVROWS*DMODEL];
__device__ __half g_Qh [QROWS*DMODEL];
__device__ __half g_Kh [KVROWS*DMODEL];
__device__ __half g_Vt [KVROWS*DMODEL];
__device__ __half g_attn_h[BBATCH*NHEADS*SQLEN*SKVLEN];
__device__ __half g_ctx_h[QROWS*DMODEL];
__device__ __half g_y_h [QROWS*DMODEL];
__device__ __half g_hh  [QROWS*DFFN];
__device__ __half g_Wqt[DMODEL*DMODEL];
__device__ __half g_Wkt[DMODEL*DMODEL];
__device__ __half g_Wvt[DMODEL*DMODEL];
__device__ __half g_Wot[DMODEL*DMODEL];
__device__ __half g_W1t[DFFN*DMODEL];
__device__ __half g_W2t[DMODEL*DFFN];
__device__ float  g_x [QROWS*DMODEL];
__device__ float  g_attn_fb[BBATCH*NHEADS*SQLEN*SKVLEN];

// ------------------ weight transposes (splittable by id) ------------------
__global__ void __launch_bounds__(256) transpose_part_kernel(
    const float* __restrict__ Wq, const float* __restrict__ Wk,
    const float* __restrict__ Wv, const float* __restrict__ Wo,
    const float* __restrict__ W1, const float* __restrict__ W2,
    __half* __restrict__ Wqt, __half* __restrict__ Wkt,
    __half* __restrict__ Wvt, __half* __restrict__ Wot,
    __half* __restrict__ W1t, __half* __restrict__ W2t, int id_base)
{
    __shared__ float t[32][33];
    const int id = blockIdx.x + id_base;
    const float* W; __half* Wt; int K, N, local, tilesX;
    if (id < 4096) {
        K = DMODEL; N = DMODEL; tilesX = 32; local = id & 1023;
        const int w = id >> 10;
        W  = (w == 0) ? Wq  : (w == 1) ? Wk  : (w == 2) ? Wv  : Wo;
        Wt = (w == 0) ? Wqt : (w == 1) ? Wkt : (w == 2) ? Wvt : Wot;
    } else if (id < 8192) {
        K = DMODEL; N = DFFN; tilesX = 128; local = id - 4096; W = W1; Wt = W1t;
    } else {
        K = DFFN; N = DMODEL; tilesX = 32; local = id - 8192; W = W2; Wt = W2t;
    }
    const int n0 = (local % tilesX) * 32, k0 = (local / tilesX) * 32;
    const int x = threadIdx.x & 31, y = threadIdx.x >> 5;
    #pragma unroll
    for (int i = 0; i < 32; i += 8)
        t[y + i][x] = W[(size_t)(k0 + y + i) * N + n0 + x];
    __syncthreads();
    #pragma unroll
    for (int i = 0; i < 32; i += 8)
        Wt[(size_t)(n0 + y + i) * K + k0 + x] = __float2half_rn(t[x][y + i]);
}

// -------------- LayerNorm, warp-per-row (8 rows / 256-thr CTA) -----------
__global__ void __launch_bounds__(256) ln_w_kernel(const float* __restrict__ x,
                                                   const float* __restrict__ g,
                                                   const float* __restrict__ b,
                                                   __half* __restrict__ y) {
    const int warp = threadIdx.x >> 5, lane = threadIdx.x & 31;
    const int row = blockIdx.x * 8 + warp;
    const float4* px = (const float4*)(x + (size_t)row * DMODEL);
    float4 v[8];
    float s = 0.f, q2 = 0.f;
    #pragma unroll
    for (int i = 0; i < 8; ++i) {
        v[i] = px[i * 32 + lane];
        s  += v[i].x + v[i].y + v[i].z + v[i].w;
        q2 += v[i].x*v[i].x + v[i].y*v[i].y + v[i].z*v[i].z + v[i].w*v[i].w;
    }
    #pragma unroll
    for (int o = 16; o > 0; o >>= 1) {
        s  += __shfl_xor_sync(0xffffffffu, s,  o);
        q2 += __shfl_xor_sync(0xffffffffu, q2, o);
    }
    const float mu  = s * (1.0f / DMODEL);
    const float inv = rsqrtf(q2 * (1.0f / DMODEL) - mu * mu + 1e-5f);
    uint2* py = (uint2*)(y + (size_t)row * DMODEL);
    #pragma unroll
    for (int i = 0; i < 8; ++i) {
        const float4 gv = ((const float4*)g)[i * 32 + lane];
        const float4 bv = ((const float4*)b)[i * 32 + lane];
        __half2 h0 = __floats2half2_rn((v[i].x - mu)*inv*gv.x + bv.x,
                                       (v[i].y - mu)*inv*gv.y + bv.y);
        __half2 h1 = __floats2half2_rn((v[i].z - mu)*inv*gv.z + bv.z,
                                       (v[i].w - mu)*inv*gv.w + bv.w);
        uint2 o2;
        o2.x = *reinterpret_cast<uint32_t*>(&h0);
        o2.y = *reinterpret_cast<uint32_t*>(&h1);
        py[i * 32 + lane] = o2;
    }
}

// -------- softmax, warp-per-row: fp32 in place + fused fp16 copy ---------
__global__ void __launch_bounds__(256) softmax_w_kernel(float* __restrict__ attn,
                                                        __half* __restrict__ attn_h) {
    const int warp = threadIdx.x >> 5, lane = threadIdx.x & 31;
    const size_t row = (size_t)blockIdx.x * 8 + warp;
    float4* p = (float4*)(attn + row * SKVLEN);
    float4 v[8];
    float m = -1e30f;
    #pragma unroll
    for (int i = 0; i < 8; ++i) {
        v[i] = p[i * 32 + lane];
        m = fmaxf(m, fmaxf(fmaxf(v[i].x, v[i].y), fmaxf(v[i].z, v[i].w)));
    }
    #pragma unroll
    for (int o = 16; o > 0; o >>= 1)
        m = fmaxf(m, __shfl_xor_sync(0xffffffffu, m, o));
    float s = 0.f;
    #pragma unroll
    for (int i = 0; i < 8; ++i) {
        v[i].x = __expf(v[i].x - m); v[i].y = __expf(v[i].y - m);
        v[i].z = __expf(v[i].z - m); v[i].w = __expf(v[i].w - m);
        s += v[i].x + v[i].y + v[i].z + v[i].w;
    }
    #pragma unroll
    for (int o = 16; o > 0; o >>= 1)
        s += __shfl_xor_sync(0xffffffffu, s, o);
    const float inv = 1.0f / s;
    uint2* ph = (uint2*)(attn_h + row * SKVLEN);
    #pragma unroll
    for (int i = 0; i < 8; ++i) {
        v[i].x *= inv; v[i].y *= inv; v[i].z *= inv; v[i].w *= inv;
        p[i * 32 + lane] = v[i];
        __half2 h0 = __floats2half2_rn(v[i].x, v[i].y);
        __half2 h1 = __floats2half2_rn(v[i].z, v[i].w);
        uint2 o2;
        o2.x = *reinterpret_cast<uint32_t*>(&h0);
        o2.y = *reinterpret_cast<uint32_t*>(&h1);
        ph[i * 32 + lane] = o2;
    }
}

// ----------------------------- fp16 MMA helpers --------------------------
__device__ __forceinline__ void ldsm4(uint32_t (&d)[4], uint32_t addr) {
    asm volatile("ldmatrix.sync.aligned.m8n8.x4.shared.b16 {%0,%1,%2,%3}, [%4];"
        : "=r"(d[0]), "=r"(d[1]), "=r"(d[2]), "=r"(d[3]) : "r"(addr));
}
__device__ __forceinline__ void mma_f16(float (&c)[4], const uint32_t (&a)[4],
                                        const uint32_t (&b)[2]) {
    asm volatile("mma.sync.aligned.m16n8k16.row.col.f32.f16.f16.f32 "
        "{%0,%1,%2,%3},{%4,%5,%6,%7},{%8,%9},{%0,%1,%2,%3};"
        : "+f"(c[0]), "+f"(c[1]), "+f"(c[2]), "+f"(c[3])
        : "r"(a[0]), "r"(a[1]), "r"(a[2]), "r"(a[3]), "r"(b[0]), "r"(b[1]));
}

// Epilogue modes
template<int MODE>
__device__ __forceinline__ void store_elem(void* __restrict__ Cv,
                                           const float* __restrict__ bias,
                                           const float* __restrict__ res,
                                           int N, int bz, int row, int col, float v) {
    if (MODE == 0) {
        ((float*)Cv)[(size_t)row*N + col] = v + bias[col];
    } else if (MODE == 1) {
        float x = v + bias[col];
        ((__half*)Cv)[(size_t)row*N + col] =
            __float2half_rn(0.5f*x*(1.0f + erff(x*0.70710678118654752f)));
    } else if (MODE == 2) {
        ((float*)Cv)[(size_t)row*N + col] = v + bias[col] + res[(size_t)row*N + col];
    } else if (MODE == 3) {
        ((__half*)Cv)[(size_t)(row>>8)*(NHEADS*SQLEN*DHEAD) + (size_t)(col>>6)*(SQLEN*DHEAD)
          + (size_t)(row&255)*DHEAD + (col&63)] = __float2half_rn(v + bias[col]);
    } else if (MODE == 4) {
        ((__half*)Cv)[(size_t)(row>>10)*(NHEADS*SKVLEN*DHEAD) + (size_t)(col>>6)*(SKVLEN*DHEAD)
          + (size_t)(row&1023)*DHEAD + (col&63)] = __float2half_rn(v + bias[col]);
    } else if (MODE == 5) {
        ((__half*)Cv)[(size_t)(row>>10)*(NHEADS*DHEAD*SKVLEN) + (size_t)(col>>6)*(DHEAD*SKVLEN)
          + (size_t)(col&63)*SKVLEN + (row&1023)] = __float2half_rn(v + bias[col]);
    } else if (MODE == 6) {
        ((float*)Cv)[(size_t)bz*(SQLEN*SKVLEN) + (size_t)row*SKVLEN + col] = v * 0.125f;
    } else if (MODE == 7) {
        ((__half*)Cv)[((size_t)(bz>>4)*SQLEN + row)*DMODEL + (size_t)(bz&15)*DHEAD + col] =
            __float2half_rn(v);
    }
}

// ---- fp16 NT GEMM (exact R14 config: BK=32, STAGES=3, frag dbl-buf) -----
template<int BM, int BN, int WM, int WN, int STAGES, int MODE>
__global__ void __launch_bounds__(WM*WN*32, 3) hgemm_nt(
    const __half* __restrict__ Ag, const __half* __restrict__ Bg,
    const float* __restrict__ bias, const float* __restrict__ res,
    void* __restrict__ Cg, int N, int K, long sA, long sB)
{
    constexpr int NTH  = WM*WN*32;
    constexpr int ROWB = 80;
    constexpr int STGB = (BM + BN) * ROWB;
    constexpr int MT = BM / (WM * 16);
    constexpr int NT = BN / (WN * 8);
    extern __shared__ __align__(16) __half dynsm[];
    const uint32_t sm0 = (uint32_t)__cvta_generic_to_shared(dynsm);

    const int tid  = threadIdx.x;
    const int warp = tid >> 5, lane = tid & 31;
    const int wm0 = (warp % WM) * (BM / WM);
    const int wn0 = (warp / WM) * (BN / WN);
    const int bm0 = blockIdx.y * BM;
    const int bn0 = blockIdx.x * BN;
    const int bz  = blockIdx.z;
    const __half* A = Ag + (size_t)bz * sA + (size_t)bm0 * K;
    const __half* B = Bg + (size_t)bz * sB + (size_t)bn0 * K;

    float acc[MT][NT][4];
    #pragma unroll
    for (int i = 0; i < MT; ++i)
        #pragma unroll
        for (int j = 0; j < NT; ++j)
            { acc[i][j][0]=0.f; acc[i][j][1]=0.f; acc[i][j][2]=0.f; acc[i][j][3]=0.f; }

    const int KT = K >> 5;

    auto prefetch = [&](int it) {
        if (it < KT) {
            const uint32_t sb = sm0 + (uint32_t)(it % STAGES) * STGB;
            const __half* Ak = A + it * 32;
            const __half* Bk = B + it * 32;
            #pragma unroll
            for (int i = tid; i < (BM + BN) * 4; i += NTH) {
                const int r = i >> 2, c = i & 3;
                uint32_t dst; const __half* src;
                if (r < BM) { dst = sb + (uint32_t)(r*ROWB + c*16); src = Ak + (size_t)r*K + c*8; }
                else { dst = sb + (uint32_t)(BM*ROWB + (r-BM)*ROWB + c*16);
                       src = Bk + (size_t)(r-BM)*K + c*8; }
                asm volatile("cp.async.cg.shared.global [%0], [%1], 16;" :: "r"(dst), "l"(src));
            }
        }
        asm volatile("cp.async.commit_group;" ::: "memory");
    };

    uint32_t afA[MT][4], bfA[NT][2], afB[MT][4], bfB[NT][2];
    const int lr = lane & 15;

    auto ldfrag = [&](uint32_t sbA, uint32_t sbB, int ks,
                      uint32_t (&af)[MT][4], uint32_t (&bf)[NT][2]) {
        const int lcb = ((lane >> 4) * 8 + ks * 16) * 2;
        #pragma unroll
        for (int mt = 0; mt < MT; ++mt)
            ldsm4(af[mt], sbA + (uint32_t)((wm0 + mt*16 + lr)*ROWB + lcb));
        #pragma unroll
        for (int nt2 = 0; nt2 < NT/2; ++nt2) {
            uint32_t d[4];
            ldsm4(d, sbB + (uint32_t)((wn0 + nt2*16 + lr)*ROWB + lcb));
            bf[nt2*2  ][0] = d[0]; bf[nt2*2  ][1] = d[2];
            bf[nt2*2+1][0] = d[1]; bf[nt2*2+1][1] = d[3];
        }
    };
    auto mma_all = [&](const uint32_t (&af)[MT][4], const uint32_t (&bf)[NT][2]) {
        #pragma unroll
        for (int mt = 0; mt < MT; ++mt)
            #pragma unroll
            for (int nt = 0; nt < NT; ++nt)
                mma_f16(acc[mt][nt], af[mt], bf[nt]);
    };

    #pragma unroll
    for (int p = 0; p < STAGES - 1; ++p) prefetch(p);
    asm volatile("cp.async.wait_group %0;" :: "n"(STAGES - 2) : "memory");
    __syncthreads();
    ldfrag(sm0, sm0 + BM*ROWB, 0, afA, bfA);

    for (int kt = 0; kt < KT; ++kt) {
        const uint32_t sbA = sm0 + (uint32_t)(kt % STAGES) * STGB;
        ldfrag(sbA, sbA + BM*ROWB, 1, afB, bfB);
        mma_all(afA, bfA);
        prefetch(kt + STAGES - 1);
        if (kt + 1 < KT) {
            asm volatile("cp.async.wait_group %0;" :: "n"(STAGES - 2) : "memory");
            __syncthreads();
            const uint32_t nA = sm0 + (uint32_t)((kt + 1) % STAGES) * STGB;
            ldfrag(nA, nA + BM*ROWB, 0, afA, bfA);
        }
        mma_all(afB, bfB);
    }

    const int g = lane >> 2, t = lane & 3;
    #pragma unroll
    for (int mt = 0; mt < MT; ++mt) {
        #pragma unroll
        for (int nt = 0; nt < NT; ++nt) {
            const int r0 = bm0 + wm0 + mt*16 + g;
            const int c0 = bn0 + wn0 + nt*8 + t*2;
            store_elem<MODE>(Cg, bias, res, N, bz, r0,     c0,     acc[mt][nt][0]);
            store_elem<MODE>(Cg, bias, res, N, bz, r0,     c0 + 1, acc[mt][nt][1]);
            store_elem<MODE>(Cg, bias, res, N, bz, r0 + 8, c0,     acc[mt][nt][2]);
            store_elem<MODE>(Cg, bias, res, N, bz, r0 + 8, c0 + 1, acc[mt][nt][3]);
        }
    }
}

// ----------------------------- launch ------------------------------------
#define SMEMB(BM, BN, S) ((S) * ((BM) + (BN)) * 80)

extern "C" void kernel_launch(void* const* d_in, const int* in_sizes, int n_in,
                              void* d_out, int out_size) {
    const float* memory = (const float*)d_in[0];
    const float* q      = (const float*)d_in[1];
    const float* Wq = (const float*)d_in[2];  const float* bq = (const float*)d_in[3];
    const float* Wk = (const float*)d_in[4];  const float* bk = (const float*)d_in[5];
    const float* Wv = (const float*)d_in[6];  const float* bv = (const float*)d_in[7];
    const float* Wo = (const float*)d_in[8];  const float* bo = (const float*)d_in[9];
    const float* g_kv = (const float*)d_in[10]; const float* b_kv = (const float*)d_in[11];
    const float* g_q  = (const float*)d_in[12]; const float* b_q  = (const float*)d_in[13];
    const float* g_ff = (const float*)d_in[14]; const float* b_ff = (const float*)d_in[15];
    const float* W1 = (const float*)d_in[16]; const float* b1 = (const float*)d_in[17];
    const float* W2 = (const float*)d_in[18]; const float* b2 = (const float*)d_in[19];

    __half *p_qln, *p_kvln, *p_Qh, *p_Kh, *p_Vt, *p_attn_h, *p_ctx, *p_y, *p_h;
    __half *p_Wqt, *p_Wkt, *p_Wvt, *p_Wot, *p_W1t, *p_W2t;
    float *p_x, *p_fb;
    cudaGetSymbolAddress((void**)&p_qln,  g_qln_h);
    cudaGetSymbolAddress((void**)&p_kvln, g_kvln_h);
    cudaGetSymbolAddress((void**)&p_Qh,   g_Qh);
    cudaGetSymbolAddress((void**)&p_Kh,   g_Kh);
    cudaGetSymbolAddress((void**)&p_Vt,   g_Vt);
    cudaGetSymbolAddress((void**)&p_attn_h, g_attn_h);
    cudaGetSymbolAddress((void**)&p_ctx,  g_ctx_h);
    cudaGetSymbolAddress((void**)&p_y,    g_y_h);
    cudaGetSymbolAddress((void**)&p_h,    g_hh);
    cudaGetSymbolAddress((void**)&p_Wqt,  g_Wqt);
    cudaGetSymbolAddress((void**)&p_Wkt,  g_Wkt);
    cudaGetSymbolAddress((void**)&p_Wvt,  g_Wvt);
    cudaGetSymbolAddress((void**)&p_Wot,  g_Wot);
    cudaGetSymbolAddress((void**)&p_W1t,  g_W1t);
    cudaGetSymbolAddress((void**)&p_W2t,  g_W2t);
    cudaGetSymbolAddress((void**)&p_x,    g_x);
    cudaGetSymbolAddress((void**)&p_fb,   g_attn_fb);

    float* out = (float*)d_out;
    float* attn = ((size_t)out_size >= OUT_ELEMS + ATTN_ELEMS) ? (out + OUT_ELEMS) : p_fb;

    cudaFuncSetAttribute(hgemm_nt<64,128,2,2,3,3>, cudaFuncAttributeMaxDynamicSharedMemorySize, SMEMB(64,128,3));
    cudaFuncSetAttribute(hgemm_nt<64,128,2,2,3,4>, cudaFuncAttributeMaxDynamicSharedMemorySize, SMEMB(64,128,3));
    cudaFuncSetAttribute(hgemm_nt<64,128,2,2,3,5>, cudaFuncAttributeMaxDynamicSharedMemorySize, SMEMB(64,128,3));
    cudaFuncSetAttribute(hgemm_nt<64,128,2,2,3,6>, cudaFuncAttributeMaxDynamicSharedMemorySize, SMEMB(64,128,3));
    cudaFuncSetAttribute(hgemm_nt<64,64,2,2,3,7>,  cudaFuncAttributeMaxDynamicSharedMemorySize, SMEMB(64,64,3));
    cudaFuncSetAttribute(hgemm_nt<64,128,2,2,3,0>, cudaFuncAttributeMaxDynamicSharedMemorySize, SMEMB(64,128,3));
    cudaFuncSetAttribute(hgemm_nt<64,128,2,2,3,1>, cudaFuncAttributeMaxDynamicSharedMemorySize, SMEMB(64,128,3));
    cudaFuncSetAttribute(hgemm_nt<64,128,2,2,3,2>, cudaFuncAttributeMaxDynamicSharedMemorySize, SMEMB(64,128,3));

    static cudaStream_t sB = nullptr, sC = nullptr;
    static cudaEvent_t ev0 = nullptr, evT = nullptr, evKV = nullptr,
                       evQ = nullptr, evV = nullptr, evFT = nullptr;
    if (sB == nullptr) {
        cudaStreamCreateWithFlags(&sB, cudaStreamNonBlocking);
        cudaStreamCreateWithFlags(&sC, cudaStreamNonBlocking);
        cudaEventCreateWithFlags(&ev0,  cudaEventDisableTiming);
        cudaEventCreateWithFlags(&evT,  cudaEventDisableTiming);
        cudaEventCreateWithFlags(&evKV, cudaEventDisableTiming);
        cudaEventCreateWithFlags(&evQ,  cudaEventDisableTiming);
        cudaEventCreateWithFlags(&evV,  cudaEventDisableTiming);
        cudaEventCreateWithFlags(&evFT, cudaEventDisableTiming);
    }
    cudaStream_t s0 = 0;

    cudaEventRecord(ev0, s0);
    cudaStreamWaitEvent(sB, ev0, 0);
    cudaStreamWaitEvent(sC, ev0, 0);

    // stream C: ALL weight transposes (QKVO first -> evT), then FFN's -> evFT
    transpose_part_kernel<<<4096, 256, 0, sC>>>(Wq, Wk, Wv, Wo, W1, W2,
        p_Wqt, p_Wkt, p_Wvt, p_Wot, p_W1t, p_W2t, 0);
    cudaEventRecord(evT, sC);
    transpose_part_kernel<<<8192, 256, 0, sC>>>(Wq, Wk, Wv, Wo, W1, W2,
        p_Wqt, p_Wkt, p_Wvt, p_Wot, p_W1t, p_W2t, 4096);
    cudaEventRecord(evFT, sC);

    // main: LN_kv immediately (overlaps transposes)
    ln_w_kernel<<<KVROWS/8, 256, 0, s0>>>(memory, g_kv, b_kv, p_kvln);
    cudaEventRecord(evKV, s0);

    // stream B: LN_q -> Q projection (after QKVO transposes)
    ln_w_kernel<<<QROWS/8, 256, 0, sB>>>(q, g_q, b_q, p_qln);
    cudaStreamWaitEvent(sB, evT, 0);
    hgemm_nt<64,128,2,2,3,3><<<dim3(8, 32), 128, SMEMB(64,128,3), sB>>>(
        p_qln, p_Wqt, bq, nullptr, p_Qh, DMODEL, DMODEL, 0, 0);
    cudaEventRecord(evQ, sB);

    // stream C: V projection (transposes done on this stream; wait LN_kv)
    cudaStreamWaitEvent(sC, evKV, 0);
    hgemm_nt<64,128,2,2,3,5><<<dim3(8, 128), 128, SMEMB(64,128,3), sC>>>(
        p_kvln, p_Wvt, bv, nullptr, p_Vt, DMODEL, DMODEL, 0, 0);
    cudaEventRecord(evV, sC);

    // main: K projection (needs QKVO transposes from sC)
    cudaStreamWaitEvent(s0, evT, 0);
    hgemm_nt<64,128,2,2,3,4><<<dim3(8, 128), 128, SMEMB(64,128,3), s0>>>(
        p_kvln, p_Wkt, bk, nullptr, p_Kh, DMODEL, DMODEL, 0, 0);

    // join Q, scores
    cudaStreamWaitEvent(s0, evQ, 0);
    hgemm_nt<64,128,2,2,3,6><<<dim3(8, 4, BBATCH*NHEADS), 128, SMEMB(64,128,3), s0>>>(
        p_Qh, p_Kh, nullptr, nullptr, attn, SKVLEN, DHEAD,
        (long)SQLEN*DHEAD, (long)SKVLEN*DHEAD);

    // softmax (warp-per-row) + fp16 copy
    softmax_w_kernel<<<(BBATCH*NHEADS*SQLEN)/8, 256, 0, s0>>>(attn, p_attn_h);

    // join V, ctx
    cudaStreamWaitEvent(s0, evV, 0);
    hgemm_nt<64,64,2,2,3,7><<<dim3(1, 4, BBATCH*NHEADS), 128, SMEMB(64,64,3), s0>>>(
        p_attn_h, p_Vt, nullptr, nullptr, p_ctx, DHEAD, SKVLEN,
        (long)SQLEN*SKVLEN, (long)DHEAD*SKVLEN);

    // O projection
    hgemm_nt<64,128,2,2,3,0><<<dim3(8, 32), 128, SMEMB(64,128,3), s0>>>(
        p_ctx, p_Wot, bo, nullptr, p_x, DMODEL, DMODEL, 0, 0);

    // FFN
    ln_w_kernel<<<QROWS/8, 256, 0, s0>>>(p_x, g_ff, b_ff, p_y);
    cudaStreamWaitEvent(s0, evFT, 0);
    hgemm_nt<64,128,2,2,3,1><<<dim3(32, 32), 128, SMEMB(64,128,3), s0>>>(
        p_y, p_W1t, b1, nullptr, p_h, DFFN, DMODEL, 0, 0);
    hgemm_nt<64,128,2,2,3,2><<<dim3(8, 32), 128, SMEMB(64,128,3), s0>>>(
        p_h, p_W2t, b2, p_x, out, DMODEL, DFFN, 0, 0);
}